// round 15
// baseline (speedup 1.0000x reference)
#include <cuda_runtime.h>
#include <cuda_fp16.h>
#include <cstdint>

#define MN  50000
#define NE  800000

// ---------------- scratch (device globals; no allocs allowed) ---------------
__device__ __half g_act[(size_t)MN * 256];      // layer-1 output (256 wide)
__device__ __half g_act2[(size_t)MN * 128];     // layer-2 output (128 wide)
__device__ __half g_wHi[6][65536];              // weights fp16 (transposed [N,K])
__device__ int g_row[MN + 1];
__device__ int g_cnt[MN];
__device__ int g_srcs[NE];

// ---------------- helpers ---------------------------------------------------
__device__ __forceinline__ uint32_t smem_u32(const void* p) {
    return (uint32_t)__cvta_generic_to_shared((void*)p);
}
__device__ __forceinline__ void cp_async16(uint32_t dst, const void* src) {
    asm volatile("cp.async.cg.shared.global [%0], [%1], 16;" :: "r"(dst), "l"(src));
}
__device__ __forceinline__ void cp_commit() {
    asm volatile("cp.async.commit_group;" ::: "memory");
}
template <int n>
__device__ __forceinline__ void cp_wait() {
    asm volatile("cp.async.wait_group %0;" :: "n"(n) : "memory");
}
__device__ __forceinline__ void ldsm_x4(uint32_t& r0, uint32_t& r1, uint32_t& r2,
                                        uint32_t& r3, uint32_t addr) {
    asm volatile("ldmatrix.sync.aligned.m8n8.x4.shared.b16 {%0,%1,%2,%3}, [%4];"
                 : "=r"(r0), "=r"(r1), "=r"(r2), "=r"(r3) : "r"(addr));
}
__device__ __forceinline__ void mma16816(float* d, const uint32_t* a, const uint32_t* b) {
    asm volatile("mma.sync.aligned.m16n8k16.row.col.f32.f16.f16.f32 "
                 "{%0,%1,%2,%3}, {%4,%5,%6,%7}, {%8,%9}, {%0,%1,%2,%3};"
                 : "+f"(d[0]), "+f"(d[1]), "+f"(d[2]), "+f"(d[3])
                 : "r"(a[0]), "r"(a[1]), "r"(a[2]), "r"(a[3]), "r"(b[0]), "r"(b[1]));
}

// ---------------- CSR build -------------------------------------------------
__global__ void k_zero_cnt() {
    int i = blockIdx.x * blockDim.x + threadIdx.x;
    if (i < MN) g_cnt[i] = 0;
}
__global__ void k_count(const int* __restrict__ ei) {
    int e = blockIdx.x * blockDim.x + threadIdx.x;
    if (e < NE) {
        int dst = ei[NE + e];
        if (dst >= 0 && dst < MN) atomicAdd(&g_cnt[dst], 1);
    }
}
__global__ void k_scan() {
    __shared__ int ssum[1024];
    const int t = threadIdx.x;
    const int CH = (MN + 1023) / 1024;
    const int base = t * CH;
    int s = 0;
    for (int i = 0; i < CH; i++) { int idx = base + i; if (idx < MN) s += g_cnt[idx]; }
    ssum[t] = s;
    __syncthreads();
    for (int off = 1; off < 1024; off <<= 1) {
        int v = (t >= off) ? ssum[t - off] : 0;
        __syncthreads();
        ssum[t] += v;
        __syncthreads();
    }
    int run = ssum[t] - s;
    for (int i = 0; i < CH; i++) {
        int idx = base + i;
        if (idx < MN) { int c = g_cnt[idx]; g_row[idx] = run; run += c; g_cnt[idx] = 0; }
    }
    if (t == 1023) g_row[MN] = ssum[1023];
}
__global__ void k_fill(const int* __restrict__ ei) {
    int e = blockIdx.x * blockDim.x + threadIdx.x;
    if (e < NE) {
        int src = ei[e];
        int dst = ei[NE + e];
        if (src >= 0 && src < MN && dst >= 0 && dst < MN) {
            int pos = atomicAdd(&g_cnt[dst], 1);
            g_srcs[g_row[dst] + pos] = src;
        }
    }
}

// ---------------- weight convert: W[K,N] fp32 -> fp16 [N,K] -----------------
__global__ void k_wcvt(const float* __restrict__ W, __half* __restrict__ hi, int K, int N) {
    __shared__ float t[32][33];
    const int kb = blockIdx.y * 32, nb = blockIdx.x * 32;
    const int tx = threadIdx.x, ty0 = threadIdx.y;
#pragma unroll
    for (int i = 0; i < 4; i++) {
        int ty = ty0 + 8 * i;
        t[ty][tx] = W[(size_t)(kb + ty) * N + nb + tx];
    }
    __syncthreads();
#pragma unroll
    for (int i = 0; i < 4; i++) {
        int n = ty0 + 8 * i;
        hi[(size_t)(nb + n) * K + kb + tx] = __float2half_rn(t[tx][n]);
    }
}

// ---------------- gather helpers --------------------------------------------
__device__ __forceinline__ float4 load4(const float* p) {
    return *(const float4*)p;
}
__device__ __forceinline__ float4 load4(const __half* p) {
    uint2 u = __ldg((const uint2*)p);
    float2 a = __half22float2(*(__half2*)&u.x);
    float2 b = __half22float2(*(__half2*)&u.y);
    return make_float4(a.x, a.y, b.x, b.y);
}

// ---------------- fused layer: gather + MLP ---------------------------------
// Per CTA (128 rows): phase0 gather-agg -> smem A; phase1 H=ReLU(A@W1+b1) -> smem;
// phase2 out = act2(H@W2+b2).
#define PITCH 40                   // fp16 elems per smem row (80B, conflict-free)
#define TILE_B 10240               // one 128x32 fp16 chunk, 80B rows

template <int NT>
__device__ __forceinline__ void load_w(uint32_t s0, const __half* __restrict__ Bh,
                                       int tid, int K, int kb) {
#pragma unroll
    for (int i = 0; i < 512 / NT; i++) {
        const int idx = tid + NT * i;
        const int r = idx >> 2, c4 = idx & 3;
        cp_async16(s0 + (uint32_t)(r * 80 + c4 * 16), Bh + (size_t)r * K + kb + c4 * 8);
    }
}

template <int JN>
__device__ __forceinline__ void compute_chunk(uint32_t sAU, uint32_t sBU,
                                              uint32_t aOffB, uint32_t bOffB,
                                              float acc[2][JN][4]) {
#pragma unroll
    for (int k16 = 0; k16 < 2; k16++) {
        const uint32_t kByte = (uint32_t)(k16 * 16 * 2);
        uint32_t a[2][4];
#pragma unroll
        for (int i = 0; i < 2; i++)
            ldsm_x4(a[i][0], a[i][1], a[i][2], a[i][3],
                    sAU + aOffB + kByte + (uint32_t)(i * 16 * PITCH * 2));
        uint32_t b2[JN][2];
#pragma unroll
        for (int jj = 0; jj < JN / 2; jj++)
            ldsm_x4(b2[2 * jj][0], b2[2 * jj][1], b2[2 * jj + 1][0], b2[2 * jj + 1][1],
                    sBU + bOffB + kByte + (uint32_t)(jj * 16 * PITCH * 2));
#pragma unroll
        for (int i = 0; i < 2; i++)
#pragma unroll
            for (int j = 0; j < JN; j++) mma16816(acc[i][j], a[i], b2[j]);
    }
}

template <int K1, int N1, int N2, int EPI2, int NWARPS, typename TIN>
__global__ __launch_bounds__(NWARPS * 32, NWARPS == 8 ? 2 : 1)
void k_flayer(const TIN* __restrict__ xin,
              const __half* __restrict__ W1h, const float* __restrict__ b1,
              const __half* __restrict__ W2h, const float* __restrict__ b2,
              float* __restrict__ outF, __half* __restrict__ outH, int M) {
    extern __shared__ char sm[];
    constexpr int NT = NWARPS * 32;
    constexpr int ACH = K1 / 32;
    constexpr int HCH = N1 / 32;
    constexpr int AOFF = 0;
    constexpr int HOFF = ACH * TILE_B;
    constexpr int POFF = HOFF + HCH * TILE_B;
    constexpr int B1OFF = POFF + 2 * TILE_B;
    constexpr int B2OFF = B1OFF + N1 * 4;
    float* sb1 = (float*)(sm + B1OFF);
    float* sb2 = (float*)(sm + B2OFF);

    const int tid = threadIdx.x, warp = tid >> 5, lane = tid & 31;
    const int g = lane >> 2, tig = lane & 3;
    constexpr int WN = NWARPS / 4;       // warps along N
    constexpr int NEXT = 128 / WN;       // warp N-extent (64 or 32)
    constexpr int JN = NEXT / 8;         // n8 tiles per warp (8 or 4)
    const int wm = warp / WN, wn = warp % WN;
    const int m0 = blockIdx.x * 128;

    if (tid < N1) sb1[tid] = b1[tid];
    if (tid < N2) sb2[tid] = b2[tid];

    const uint32_t smu = smem_u32(sm);
    const int aRow = wm * 32 + (lane & 15);
    const int aCol = (lane & 16) ? 8 : 0;
    const uint32_t aOffB = (uint32_t)(aRow * PITCH + aCol) * 2;
    const int bRow = wn * NEXT + (lane & 7) + ((lane & 16) ? 8 : 0);
    const int bCol = (lane & 8) ? 8 : 0;
    const uint32_t bOffB = (uint32_t)(bRow * PITCH + bCol) * 2;

    // ---------------- phase 0: gather-aggregate -> smem A (PITCH chunks) ----
    constexpr int NPW = 128 / NWARPS;    // nodes per warp
    constexpr int VEC = K1 / 128;
    for (int nn = 0; nn < NPW; nn++) {
        const int row = warp * NPW + nn;
        const int node = m0 + row;
        float4 acc0[VEC], acc1[VEC];
#pragma unroll
        for (int v = 0; v < VEC; v++) {
            acc0[v] = make_float4(0.f, 0.f, 0.f, 0.f);
            acc1[v] = make_float4(0.f, 0.f, 0.f, 0.f);
        }
        if (node < MN) {
#pragma unroll
            for (int v = 0; v < VEC; v++)
                acc0[v] = load4(xin + (size_t)node * K1 + (lane + 32 * v) * 4);
            const int s = g_row[node];
            const int e = g_row[node + 1];
            for (int i = s; i < e; i += 32) {
                const int my = (i + lane < e) ? g_srcs[i + lane] : 0;
                const int cnt = min(32, e - i);
                int t = 0;
                for (; t + 2 <= cnt; t += 2) {
                    const int s0 = __shfl_sync(0xffffffff, my, t);
                    const int s1 = __shfl_sync(0xffffffff, my, t + 1);
                    const TIN* p0 = xin + (size_t)s0 * K1;
                    const TIN* p1 = xin + (size_t)s1 * K1;
#pragma unroll
                    for (int v = 0; v < VEC; v++) {
                        float4 q0 = load4(p0 + (lane + 32 * v) * 4);
                        float4 q1 = load4(p1 + (lane + 32 * v) * 4);
                        acc0[v].x += q0.x; acc0[v].y += q0.y; acc0[v].z += q0.z; acc0[v].w += q0.w;
                        acc1[v].x += q1.x; acc1[v].y += q1.y; acc1[v].z += q1.z; acc1[v].w += q1.w;
                    }
                }
                if (t < cnt) {
                    const int s0 = __shfl_sync(0xffffffff, my, t);
                    const TIN* p0 = xin + (size_t)s0 * K1;
#pragma unroll
                    for (int v = 0; v < VEC; v++) {
                        float4 q0 = load4(p0 + (lane + 32 * v) * 4);
                        acc0[v].x += q0.x; acc0[v].y += q0.y; acc0[v].z += q0.z; acc0[v].w += q0.w;
                    }
                }
            }
        }
#pragma unroll
        for (int v = 0; v < VEC; v++) {
            __half2 p0 = __floats2half2_rn(acc0[v].x + acc1[v].x, acc0[v].y + acc1[v].y);
            __half2 p1 = __floats2half2_rn(acc0[v].z + acc1[v].z, acc0[v].w + acc1[v].w);
            // cols [lane*4 + 128v, +4) -> chunk (lane/8 + 4v), in-chunk col (lane%8)*4
            const uint32_t off = (uint32_t)((lane / 8 + 4 * v) * TILE_B +
                                            row * 80 + (lane % 8) * 8);
            *(uint2*)(sm + AOFF + off) = make_uint2(*(uint32_t*)&p0, *(uint32_t*)&p1);
        }
    }
    __syncthreads();

    float acc[2][JN][4];

    // ---------------- phase 1: H = ReLU(A@W1 + b1) -> smem -------------------
#pragma unroll
    for (int n1t = 0; n1t < N1 / 128; n1t++) {
#pragma unroll
        for (int i = 0; i < 2; i++)
#pragma unroll
            for (int j = 0; j < JN; j++)
#pragma unroll
                for (int r = 0; r < 4; r++) acc[i][j][r] = 0.f;

        const __half* W1T = W1h + (size_t)n1t * 128 * K1;
        constexpr int NKT = K1 / 32;
        load_w<NT>(smu + POFF, W1T, tid, K1, 0);
        cp_commit();
        for (int kt = 0; kt < NKT; kt++) {
            const int b = kt & 1;
            if (kt + 1 < NKT) {
                __syncthreads();
                load_w<NT>(smu + POFF + (b ^ 1) * TILE_B, W1T, tid, K1, (kt + 1) * 32);
                cp_commit();
                cp_wait<1>();
            } else {
                cp_wait<0>();
            }
            __syncthreads();
            compute_chunk<JN>(smu + AOFF + kt * TILE_B, smu + POFF + b * TILE_B,
                              aOffB, bOffB, acc);
        }
        // epilogue: ReLU + fp16 into H chunks
#pragma unroll
        for (int i = 0; i < 2; i++) {
#pragma unroll
            for (int hf = 0; hf < 2; hf++) {
                const int row = wm * 32 + i * 16 + g + hf * 8;
#pragma unroll
                for (int j = 0; j < JN; j++) {
                    const int col = wn * NEXT + j * 8 + tig * 2;
                    float v0 = fmaxf(acc[i][j][2 * hf + 0] + sb1[n1t * 128 + col], 0.f);
                    float v1 = fmaxf(acc[i][j][2 * hf + 1] + sb1[n1t * 128 + col + 1], 0.f);
                    __half2 hp = __floats2half2_rn(v0, v1);
                    const uint32_t hoff = (uint32_t)((n1t * 4 + (col >> 5)) * TILE_B +
                                                     row * 80 + (col & 31) * 2);
                    *(uint32_t*)(sm + HOFF + hoff) = *(uint32_t*)&hp;
                }
            }
        }
        __syncthreads();
    }

    // ---------------- phase 2: out = act2(H@W2 + b2) -------------------------
#pragma unroll
    for (int n2t = 0; n2t < N2 / 128; n2t++) {
#pragma unroll
        for (int i = 0; i < 2; i++)
#pragma unroll
            for (int j = 0; j < JN; j++)
#pragma unroll
                for (int r = 0; r < 4; r++) acc[i][j][r] = 0.f;

        const __half* W2T = W2h + (size_t)n2t * 128 * N1;
        constexpr int NKT2 = N1 / 32;
        load_w<NT>(smu + POFF, W2T, tid, N1, 0);
        cp_commit();
        for (int kt = 0; kt < NKT2; kt++) {
            const int b = kt & 1;
            if (kt + 1 < NKT2) {
                __syncthreads();
                load_w<NT>(smu + POFF + (b ^ 1) * TILE_B, W2T, tid, N1, (kt + 1) * 32);
                cp_commit();
                cp_wait<1>();
            } else {
                cp_wait<0>();
            }
            __syncthreads();
            compute_chunk<JN>(smu + HOFF + kt * TILE_B, smu + POFF + b * TILE_B,
                              aOffB, bOffB, acc);
        }
#pragma unroll
        for (int i = 0; i < 2; i++) {
#pragma unroll
            for (int hf = 0; hf < 2; hf++) {
                const int row = m0 + wm * 32 + i * 16 + g + hf * 8;
                if (row >= M) continue;
#pragma unroll
                for (int j = 0; j < JN; j++) {
                    const int cl = wn * NEXT + j * 8 + tig * 2;
                    float v0 = acc[i][j][2 * hf + 0] + sb2[n2t * 128 + cl];
                    float v1 = acc[i][j][2 * hf + 1] + sb2[n2t * 128 + cl + 1];
                    const size_t o = (size_t)row * N2 + n2t * 128 + cl;
                    if (EPI2 == 0) {
                        v0 = fmaxf(v0, 0.f);
                        v1 = fmaxf(v1, 0.f);
                        __half2 hp = __floats2half2_rn(v0, v1);
                        *(uint32_t*)(outH + o) = *(uint32_t*)&hp;
                    } else {
                        *(float2*)(outF + o) = make_float2(v0, v1);
                    }
                }
            }
        }
        __syncthreads();
    }
}

// ---------------- launch ----------------------------------------------------
extern "C" void kernel_launch(void* const* d_in, const int* in_sizes, int n_in,
                              void* d_out, int out_size) {
    const float* x  = (const float*)d_in[0];
    const int*   ei = (const int*)d_in[1];   // int32 (JAX x64 disabled)
    const float* W[6]  = {(const float*)d_in[2], (const float*)d_in[4], (const float*)d_in[6],
                          (const float*)d_in[8], (const float*)d_in[10], (const float*)d_in[12]};
    const float* Bv[6] = {(const float*)d_in[3], (const float*)d_in[5], (const float*)d_in[7],
                          (const float*)d_in[9], (const float*)d_in[11], (const float*)d_in[13]};
    const int WK[6] = {128, 128, 256, 256, 128, 128};
    const int WN6[6] = {128, 256, 256, 128, 128, 128};
    float* out = (float*)d_out;

    __half *act, *act2, *wHi;
    cudaGetSymbolAddress((void**)&act, g_act);
    cudaGetSymbolAddress((void**)&act2, g_act2);
    cudaGetSymbolAddress((void**)&wHi, g_wHi);

    // smem from template formula: (ACH + HCH + 2)*TILE_B + (N1+N2)*4
    const int SM_L1 = (4 + 4 + 2) * TILE_B + (128 + 256) * 4;   // 103936
    const int SM_L2 = (8 + 8 + 2) * TILE_B + (256 + 128) * 4;   // 185856
    const int SM_L3 = (4 + 4 + 2) * TILE_B + (128 + 128) * 4;   // 103424
    cudaFuncSetAttribute((k_flayer<128, 128, 256, 0, 8, float>),
                         cudaFuncAttributeMaxDynamicSharedMemorySize, SM_L1);
    cudaFuncSetAttribute((k_flayer<256, 256, 128, 0, 16, __half>),
                         cudaFuncAttributeMaxDynamicSharedMemorySize, SM_L2);
    cudaFuncSetAttribute((k_flayer<128, 128, 128, 1, 8, __half>),
                         cudaFuncAttributeMaxDynamicSharedMemorySize, SM_L3);

    // --- CSR build ---
    k_zero_cnt<<<(MN + 255) / 256, 256>>>();
    k_count<<<(NE + 255) / 256, 256>>>(ei);
    k_scan<<<1, 1024>>>();
    k_fill<<<(NE + 255) / 256, 256>>>(ei);

    // --- weight conversion (tiled transpose + fp16) ---
    for (int i = 0; i < 6; i++) {
        dim3 g(WN6[i] / 32, WK[i] / 32), blk(32, 8);
        k_wcvt<<<g, blk>>>(W[i], wHi + (size_t)i * 65536, WK[i], WN6[i]);
    }

    const int GRID = (MN + 127) / 128;   // 391

    // --- layer 1: gather fp32 x -> act (256 wide) ---
    k_flayer<128, 128, 256, 0, 8, float><<<GRID, 256, SM_L1>>>(
        x, wHi + 0 * 65536, Bv[0], wHi + 1 * 65536, Bv[1], nullptr, act, MN);

    // --- layer 2: gather act -> act2 (128 wide); separate buffers, no aliasing ---
    k_flayer<256, 256, 128, 0, 16, __half><<<GRID, 512, SM_L2>>>(
        act, wHi + 2 * 65536, Bv[2], wHi + 3 * 65536, Bv[3], nullptr, act2, MN);

    // --- layer 3: gather act2 -> fp32 out ---
    k_flayer<128, 128, 128, 1, 8, __half><<<GRID, 256, SM_L3>>>(
        act2, wHi + 4 * 65536, Bv[4], wHi + 5 * 65536, Bv[5], out, nullptr, MN);
}

// round 17
// speedup vs baseline: 1.3727x; 1.3727x over previous
#include <cuda_runtime.h>
#include <cuda_fp16.h>
#include <cstdint>

#define MN  50000
#define MNP 50176          // padded to 392*128 (unconditional GEMM tile loads)
#define NE  800000

// ---------------- scratch (device globals; no allocs allowed) ---------------
__device__ __half g_x16[(size_t)MNP * 128];     // fp16 copy of input x
__device__ __half g_agg[(size_t)MNP * 256];     // aggregation out (layer A input)
__device__ __half g_act[(size_t)MNP * 256];     // layer output (next agg input)
__device__ __half g_wHi[6][65536];              // weights fp16 (transposed [N,K])
__device__ int g_row[MN + 1];
__device__ int g_cnt[MN];
__device__ int g_srcs[NE];

// ---------------- helpers ---------------------------------------------------
__device__ __forceinline__ uint32_t smem_u32(const void* p) {
    return (uint32_t)__cvta_generic_to_shared((void*)p);
}
__device__ __forceinline__ void cp_async16(uint32_t dst, const void* src) {
    asm volatile("cp.async.cg.shared.global [%0], [%1], 16;" :: "r"(dst), "l"(src));
}
__device__ __forceinline__ void cp_commit() {
    asm volatile("cp.async.commit_group;" ::: "memory");
}
template <int n>
__device__ __forceinline__ void cp_wait() {
    asm volatile("cp.async.wait_group %0;" :: "n"(n) : "memory");
}
__device__ __forceinline__ void ldsm_x4(uint32_t& r0, uint32_t& r1, uint32_t& r2,
                                        uint32_t& r3, uint32_t addr) {
    asm volatile("ldmatrix.sync.aligned.m8n8.x4.shared.b16 {%0,%1,%2,%3}, [%4];"
                 : "=r"(r0), "=r"(r1), "=r"(r2), "=r"(r3) : "r"(addr));
}
__device__ __forceinline__ void mma16816(float* d, const uint32_t* a, const uint32_t* b) {
    asm volatile("mma.sync.aligned.m16n8k16.row.col.f32.f16.f16.f32 "
                 "{%0,%1,%2,%3}, {%4,%5,%6,%7}, {%8,%9}, {%0,%1,%2,%3};"
                 : "+f"(d[0]), "+f"(d[1]), "+f"(d[2]), "+f"(d[3])
                 : "r"(a[0]), "r"(a[1]), "r"(a[2]), "r"(a[3]), "r"(b[0]), "r"(b[1]));
}

// ---------------- CSR build -------------------------------------------------
__global__ void k_zero_cnt() {
    int i = blockIdx.x * blockDim.x + threadIdx.x;
    if (i < MN) g_cnt[i] = 0;
}
__global__ void k_count(const int* __restrict__ ei) {
    int e = blockIdx.x * blockDim.x + threadIdx.x;
    if (e < NE) {
        int dst = ei[NE + e];
        if (dst >= 0 && dst < MN) atomicAdd(&g_cnt[dst], 1);
    }
}
__global__ void k_scan() {
    __shared__ int ssum[1024];
    const int t = threadIdx.x;
    const int CH = (MN + 1023) / 1024;
    const int base = t * CH;
    int s = 0;
    for (int i = 0; i < CH; i++) { int idx = base + i; if (idx < MN) s += g_cnt[idx]; }
    ssum[t] = s;
    __syncthreads();
    for (int off = 1; off < 1024; off <<= 1) {
        int v = (t >= off) ? ssum[t - off] : 0;
        __syncthreads();
        ssum[t] += v;
        __syncthreads();
    }
    int run = ssum[t] - s;
    for (int i = 0; i < CH; i++) {
        int idx = base + i;
        if (idx < MN) { int c = g_cnt[idx]; g_row[idx] = run; run += c; g_cnt[idx] = 0; }
    }
    if (t == 1023) g_row[MN] = ssum[1023];
}
__global__ void k_fill(const int* __restrict__ ei) {
    int e = blockIdx.x * blockDim.x + threadIdx.x;
    if (e < NE) {
        int src = ei[e];
        int dst = ei[NE + e];
        if (src >= 0 && src < MN && dst >= 0 && dst < MN) {
            int pos = atomicAdd(&g_cnt[dst], 1);
            g_srcs[g_row[dst] + pos] = src;
        }
    }
}

// ---------------- input convert: x fp32 -> fp16 -----------------------------
__global__ void k_xcvt(const float* __restrict__ x, __half* __restrict__ o) {
    int i = blockIdx.x * blockDim.x + threadIdx.x;   // one float4 per thread
    if (i < MN * 128 / 4) {
        float4 v = *(const float4*)(x + i * 4);
        __half2 p0 = __floats2half2_rn(v.x, v.y);
        __half2 p1 = __floats2half2_rn(v.z, v.w);
        *(uint2*)(o + (size_t)i * 4) = make_uint2(*(uint32_t*)&p0, *(uint32_t*)&p1);
    }
}

// ---------------- weight convert: W[K,N] fp32 -> fp16 [N,K] -----------------
__global__ void k_wcvt(const float* __restrict__ W, __half* __restrict__ hi, int K, int N) {
    __shared__ float t[32][33];
    const int kb = blockIdx.y * 32, nb = blockIdx.x * 32;
    const int tx = threadIdx.x, ty0 = threadIdx.y;
#pragma unroll
    for (int i = 0; i < 4; i++) {
        int ty = ty0 + 8 * i;
        t[ty][tx] = W[(size_t)(kb + ty) * N + nb + tx];
    }
    __syncthreads();
#pragma unroll
    for (int i = 0; i < 4; i++) {
        int n = ty0 + 8 * i;
        hi[(size_t)(nb + n) * K + kb + tx] = __float2half_rn(t[tx][n]);
    }
}

// ---------------- aggregation: fp16 in -> fp16 out, fp32 accum --------------
__device__ __forceinline__ float4 load4h(const __half* p) {
    uint2 u = __ldg((const uint2*)p);
    float2 a = __half22float2(*(__half2*)&u.x);
    float2 b = __half22float2(*(__half2*)&u.y);
    return make_float4(a.x, a.y, b.x, b.y);
}

template <int VEC>
__global__ void k_agg(const __half* __restrict__ x, __half* __restrict__ oh) {
    const int node = (blockIdx.x * blockDim.x + threadIdx.x) >> 5;
    if (node >= MN) return;
    const int lane = threadIdx.x & 31;
    const int F = VEC * 128;

    float4 acc0[VEC], acc1[VEC];
#pragma unroll
    for (int v = 0; v < VEC; v++) {
        acc0[v] = load4h(x + (size_t)node * F + (lane + 32 * v) * 4);
        acc1[v] = make_float4(0.f, 0.f, 0.f, 0.f);
    }

    const int s = g_row[node];
    const int e = g_row[node + 1];
    for (int i = s; i < e; i += 32) {
        const int my = (i + lane < e) ? g_srcs[i + lane] : 0;
        const int cnt = min(32, e - i);
        int t = 0;
        for (; t + 2 <= cnt; t += 2) {
            const int s0 = __shfl_sync(0xffffffff, my, t);
            const int s1 = __shfl_sync(0xffffffff, my, t + 1);
            const __half* p0 = x + (size_t)s0 * F;
            const __half* p1 = x + (size_t)s1 * F;
#pragma unroll
            for (int v = 0; v < VEC; v++) {
                float4 q0 = load4h(p0 + (lane + 32 * v) * 4);
                float4 q1 = load4h(p1 + (lane + 32 * v) * 4);
                acc0[v].x += q0.x; acc0[v].y += q0.y; acc0[v].z += q0.z; acc0[v].w += q0.w;
                acc1[v].x += q1.x; acc1[v].y += q1.y; acc1[v].z += q1.z; acc1[v].w += q1.w;
            }
        }
        if (t < cnt) {
            const int s0 = __shfl_sync(0xffffffff, my, t);
            const __half* p0 = x + (size_t)s0 * F;
#pragma unroll
            for (int v = 0; v < VEC; v++) {
                float4 q0 = load4h(p0 + (lane + 32 * v) * 4);
                acc0[v].x += q0.x; acc0[v].y += q0.y; acc0[v].z += q0.z; acc0[v].w += q0.w;
            }
        }
    }
#pragma unroll
    for (int v = 0; v < VEC; v++) {
        __half2 p0 = __floats2half2_rn(acc0[v].x + acc1[v].x, acc0[v].y + acc1[v].y);
        __half2 p1 = __floats2half2_rn(acc0[v].z + acc1[v].z, acc0[v].w + acc1[v].w);
        size_t off = (size_t)node * F + (lane + 32 * v) * 4;
        *(uint2*)(oh + off) = make_uint2(*(uint32_t*)&p0, *(uint32_t*)&p1);
    }
}

// ---------------- fused layer: C2 = act2(ReLU(A@W1+b1)@W2 + b2) --------------
// A [M,K1] fp16; W1 [N1,K1] fp16; W2 [N2,N1] fp16. Hidden kept in SMEM.
// EPI2: 0 = fp16 + ReLU (to act buffer), 1 = fp32 (final output)
#define PITCH 40                   // fp16 elems per smem row (80B, conflict-free)
#define TILE_B 10240               // one 128x32 fp16 array, 80B rows
#define PIPE_B (2 * 2 * TILE_B)    // 2 stages x (A, W)

// phase-1 loader: A tile + W1 tile
__device__ __forceinline__ void load_aw(char* smbase, const __half* __restrict__ A,
                                        const __half* __restrict__ Bh,
                                        int tid, int m0, int K, int kb) {
    const uint32_t s0 = smem_u32(smbase);
#pragma unroll
    for (int i = 0; i < 2; i++) {
        const int idx = tid + 256 * i;
        const int r = idx >> 2, c4 = idx & 3;
        const uint32_t so = (uint32_t)(r * 80 + c4 * 16);
        cp_async16(s0 + so,          A  + (size_t)(m0 + r) * K + kb + c4 * 8);
        cp_async16(s0 + TILE_B + so, Bh + (size_t)r * K + kb + c4 * 8);
    }
}
// phase-2 loader: W2 tile only
__device__ __forceinline__ void load_w(char* smbase, const __half* __restrict__ Bh,
                                       int tid, int K, int kb) {
    const uint32_t s0 = smem_u32(smbase);
#pragma unroll
    for (int i = 0; i < 2; i++) {
        const int idx = tid + 256 * i;
        const int r = idx >> 2, c4 = idx & 3;
        const uint32_t so = (uint32_t)(r * 80 + c4 * 16);
        cp_async16(s0 + so, Bh + (size_t)r * K + kb + c4 * 8);
    }
}

__device__ __forceinline__ void compute_chunk(uint32_t sAU, uint32_t sBU,
                                              uint32_t aOffB, uint32_t bOffB,
                                              float acc[2][8][4]) {
#pragma unroll
    for (int k16 = 0; k16 < 2; k16++) {
        const uint32_t kByte = (uint32_t)(k16 * 16 * 2);
        uint32_t a[2][4];
#pragma unroll
        for (int i = 0; i < 2; i++)
            ldsm_x4(a[i][0], a[i][1], a[i][2], a[i][3],
                    sAU + aOffB + kByte + (uint32_t)(i * 16 * PITCH * 2));
        uint32_t b2[8][2];
#pragma unroll
        for (int jj = 0; jj < 4; jj++)
            ldsm_x4(b2[2 * jj][0], b2[2 * jj][1], b2[2 * jj + 1][0], b2[2 * jj + 1][1],
                    sBU + bOffB + kByte + (uint32_t)(jj * 16 * PITCH * 2));
#pragma unroll
        for (int i = 0; i < 2; i++)
#pragma unroll
            for (int j = 0; j < 8; j++) mma16816(acc[i][j], a[i], b2[j]);
    }
}

template <int K1, int N1, int N2, int EPI2>
__global__ __launch_bounds__(256, 2)
void k_layer(const __half* __restrict__ A,
             const __half* __restrict__ W1h, const float* __restrict__ b1,
             const __half* __restrict__ W2h, const float* __restrict__ b2,
             float* __restrict__ outF, __half* __restrict__ outH, int M) {
    extern __shared__ char sm[];
    constexpr int HCH = N1 / 32;                       // H chunks (K of phase 2)
    constexpr int HOFF = PIPE_B;
    constexpr int B1OFF = HOFF + HCH * TILE_B;
    constexpr int B2OFF = B1OFF + N1 * 4;
    float* sb1 = (float*)(sm + B1OFF);
    float* sb2 = (float*)(sm + B2OFF);

    const int tid = threadIdx.x, warp = tid >> 5, lane = tid & 31;
    const int g = lane >> 2, tig = lane & 3;
    const int wm = warp >> 1, wn = warp & 1;           // 4x2 warp grid, 32x64 tile
    const int m0 = blockIdx.x * 128;

    if (tid < N1) sb1[tid] = b1[tid];
    if (tid < N2) sb2[tid] = b2[tid];

    const int aRow = wm * 32 + (lane & 15);
    const int aCol = (lane & 16) ? 8 : 0;
    const uint32_t aOffB = (uint32_t)(aRow * PITCH + aCol) * 2;
    const int bRow = wn * 64 + (lane & 7) + ((lane & 16) ? 8 : 0);
    const int bCol = (lane & 8) ? 8 : 0;
    const uint32_t bOffB = (uint32_t)(bRow * PITCH + bCol) * 2;

    const uint32_t smu = smem_u32(sm);
    const uint32_t Hu = smu + HOFF;
    float acc[2][8][4];

    // ---------------- phase 1: H = ReLU(A@W1 + b1) -> smem ----------------
    __syncthreads();   // biases visible
#pragma unroll
    for (int n1t = 0; n1t < N1 / 128; n1t++) {
#pragma unroll
        for (int i = 0; i < 2; i++)
#pragma unroll
            for (int j = 0; j < 8; j++)
#pragma unroll
                for (int r = 0; r < 4; r++) acc[i][j][r] = 0.f;

        const __half* W1T = W1h + (size_t)n1t * 128 * K1;
        constexpr int NKT = K1 / 32;
        load_aw(sm, A, W1T, tid, m0, K1, 0);
        cp_commit();
        for (int kt = 0; kt < NKT; kt++) {
            const int b = kt & 1;
            if (kt + 1 < NKT) {
                __syncthreads();
                load_aw(sm + (b ^ 1) * 2 * TILE_B, A, W1T, tid, m0, K1, (kt + 1) * 32);
                cp_commit();
                cp_wait<1>();
            } else {
                cp_wait<0>();
            }
            __syncthreads();
            const uint32_t sAU = smu + b * 2 * TILE_B;
            compute_chunk(sAU, sAU + TILE_B, aOffB, bOffB, acc);
        }
        // epilogue: ReLU + fp16 into H chunks (PITCH layout)
#pragma unroll
        for (int i = 0; i < 2; i++) {
#pragma unroll
            for (int hf = 0; hf < 2; hf++) {
                const int row = wm * 32 + i * 16 + g + hf * 8;
#pragma unroll
                for (int j = 0; j < 8; j++) {
                    const int col = wn * 64 + j * 8 + tig * 2;
                    float v0 = fmaxf(acc[i][j][2 * hf + 0] + sb1[n1t * 128 + col], 0.f);
                    float v1 = fmaxf(acc[i][j][2 * hf + 1] + sb1[n1t * 128 + col + 1], 0.f);
                    __half2 hp = __floats2half2_rn(v0, v1);
                    const uint32_t hoff = (uint32_t)((n1t * 4 + (col >> 5)) * TILE_B +
                                                     row * 80 + (col & 31) * 2);
                    *(uint32_t*)(sm + HOFF + hoff) = *(uint32_t*)&hp;
                }
            }
        }
        __syncthreads();   // H chunk complete; pipe buffers free
    }

    // ---------------- phase 2: C2 = H@W2 + b2 ----------------
#pragma unroll
    for (int n2t = 0; n2t < N2 / 128; n2t++) {
#pragma unroll
        for (int i = 0; i < 2; i++)
#pragma unroll
            for (int j = 0; j < 8; j++)
#pragma unroll
                for (int r = 0; r < 4; r++) acc[i][j][r] = 0.f;

        const __half* W2T = W2h + (size_t)n2t * 128 * N1;
        constexpr int NKT2 = N1 / 32;
        load_w(sm, W2T, tid, N1, 0);
        cp_commit();
        for (int kt = 0; kt < NKT2; kt++) {
            const int b = kt & 1;
            if (kt + 1 < NKT2) {
                __syncthreads();
                load_w(sm + (b ^ 1) * TILE_B, W2T, tid, N1, (kt + 1) * 32);
                cp_commit();
                cp_wait<1>();
            } else {
                cp_wait<0>();
            }
            __syncthreads();
            compute_chunk(Hu + kt * TILE_B, smu + b * TILE_B, aOffB, bOffB, acc);
        }
        // epilogue to global
#pragma unroll
        for (int i = 0; i < 2; i++) {
#pragma unroll
            for (int hf = 0; hf < 2; hf++) {
                const int row = m0 + wm * 32 + i * 16 + g + hf * 8;
                if (row >= M) continue;
#pragma unroll
                for (int j = 0; j < 8; j++) {
                    const int cl = wn * 64 + j * 8 + tig * 2;
                    float v0 = acc[i][j][2 * hf + 0] + sb2[n2t * 128 + cl];
                    float v1 = acc[i][j][2 * hf + 1] + sb2[n2t * 128 + cl + 1];
                    const size_t o = (size_t)row * N2 + n2t * 128 + cl;
                    if (EPI2 == 0) {
                        v0 = fmaxf(v0, 0.f);
                        v1 = fmaxf(v1, 0.f);
                        __half2 hp = __floats2half2_rn(v0, v1);
                        *(uint32_t*)(outH + o) = *(uint32_t*)&hp;
                    } else {
                        *(float2*)(outF + o) = make_float2(v0, v1);
                    }
                }
            }
        }
        __syncthreads();   // protect W2 stage reuse across n2t
    }
}

// ---------------- launch ----------------------------------------------------
extern "C" void kernel_launch(void* const* d_in, const int* in_sizes, int n_in,
                              void* d_out, int out_size) {
    const float* x  = (const float*)d_in[0];
    const int*   ei = (const int*)d_in[1];   // int32 (JAX x64 disabled)
    const float* W[6]  = {(const float*)d_in[2], (const float*)d_in[4], (const float*)d_in[6],
                          (const float*)d_in[8], (const float*)d_in[10], (const float*)d_in[12]};
    const float* Bv[6] = {(const float*)d_in[3], (const float*)d_in[5], (const float*)d_in[7],
                          (const float*)d_in[9], (const float*)d_in[11], (const float*)d_in[13]};
    const int WK[6] = {128, 128, 256, 256, 128, 128};
    const int WN6[6] = {128, 256, 256, 128, 128, 128};
    float* out = (float*)d_out;

    __half *x16, *agg, *act, *wHi;
    cudaGetSymbolAddress((void**)&x16, g_x16);
    cudaGetSymbolAddress((void**)&agg, g_agg);
    cudaGetSymbolAddress((void**)&act, g_act);
    cudaGetSymbolAddress((void**)&wHi, g_wHi);

    // smem sizes per layer template
    const int SM_L1 = PIPE_B + 4 * TILE_B + (128 + 256) * 4;   // 83456
    const int SM_L2 = PIPE_B + 8 * TILE_B + (256 + 128) * 4;   // 124416
    const int SM_L3 = PIPE_B + 4 * TILE_B + (128 + 128) * 4;   // 82944
    cudaFuncSetAttribute((k_layer<128, 128, 256, 0>), cudaFuncAttributeMaxDynamicSharedMemorySize, SM_L1);
    cudaFuncSetAttribute((k_layer<256, 256, 128, 0>), cudaFuncAttributeMaxDynamicSharedMemorySize, SM_L2);
    cudaFuncSetAttribute((k_layer<128, 128, 128, 1>), cudaFuncAttributeMaxDynamicSharedMemorySize, SM_L3);

    // --- CSR build ---
    k_zero_cnt<<<(MN + 255) / 256, 256>>>();
    k_count<<<(NE + 255) / 256, 256>>>(ei);
    k_scan<<<1, 1024>>>();
    k_fill<<<(NE + 255) / 256, 256>>>(ei);

    // --- input + weight conversion ---
    k_xcvt<<<(MN * 128 / 4 + 255) / 256, 256>>>(x, x16);
    for (int i = 0; i < 6; i++) {
        dim3 g(WN6[i] / 32, WK[i] / 32), blk(32, 8);
        k_wcvt<<<g, blk>>>(W[i], wHi + (size_t)i * 65536, WK[i], WN6[i]);
    }

    const int AGG_BLOCKS = (MN * 32 + 255) / 256;
    const int GRID = MNP / 128;   // 392

    // --- layer 1 (fp16 gather of converted x) ---
    k_agg<1><<<AGG_BLOCKS, 256>>>(x16, agg);
    k_layer<128, 128, 256, 0><<<GRID, 256, SM_L1>>>(
        agg, wHi + 0 * 65536, Bv[0], wHi + 1 * 65536, Bv[1], nullptr, act, MN);

    // --- layer 2 ---
    k_agg<2><<<AGG_BLOCKS, 256>>>(act, agg);
    k_layer<256, 256, 128, 0><<<GRID, 256, SM_L2>>>(
        agg, wHi + 2 * 65536, Bv[2], wHi + 3 * 65536, Bv[3], nullptr, act, MN);

    // --- layer 3 ---
    k_agg<1><<<AGG_BLOCKS, 256>>>(act, agg);
    k_layer<128, 128, 128, 1><<<GRID, 256, SM_L3>>>(
        agg, wHi + 4 * 65536, Bv[4], wHi + 5 * 65536, Bv[5], out, nullptr, MN);
}